// round 10
// baseline (speedup 1.0000x reference)
#include <cuda_runtime.h>

#define BB 256
#define NN 512
#define INF 10
#define HIDF 32
#define R 16                      // rows per block
#define WARPS 8
#define THREADS (WARPS * 32)
#define CHUNKS (NN / R)           // 32

typedef unsigned long long u64;

// ---- packed f32x2 helpers (sm_103a FFMA2 path, PTX-only) -------------------
__device__ __forceinline__ u64 pk2(float lo, float hi) {
    u64 r; asm("mov.b64 %0,{%1,%2};" : "=l"(r) : "f"(lo), "f"(hi)); return r;
}
__device__ __forceinline__ void upk2(u64 v, float& lo, float& hi) {
    asm("mov.b64 {%0,%1},%2;" : "=f"(lo), "=f"(hi) : "l"(v));
}
__device__ __forceinline__ u64 fma2(u64 a, u64 b, u64 c) {
    u64 r; asm("fma.rn.f32x2 %0,%1,%2,%3;" : "=l"(r) : "l"(a), "l"(b), "l"(c)); return r;
}
__device__ __forceinline__ u64 mul2f(u64 a, u64 b) {
    u64 r; asm("mul.rn.f32x2 %0,%1,%2;" : "=l"(r) : "l"(a), "l"(b)); return r;
}
__device__ __forceinline__ u64 add2f(u64 a, u64 b) {
    u64 r; asm("add.rn.f32x2 %0,%1,%2;" : "=l"(r) : "l"(a), "l"(b)); return r;
}

__device__ float g_M[INF * INF];  // M = Q @ K^T

// ---------------------------------------------------------------------------
__global__ void compute_M_kernel(const float* __restrict__ Qw,
                                 const float* __restrict__ Kw) {
    int idx = threadIdx.x;
    if (idx < INF * INF) {
        int a = idx / INF, p = idx % INF;
        float acc = 0.0f;
#pragma unroll
        for (int m = 0; m < HIDF; m++)
            acc = fmaf(Qw[a * HIDF + m], Kw[p * HIDF + m], acc);
        g_M[idx] = acc;
    }
}

// ---------------------------------------------------------------------------
// Block = (batch b, 16-row chunk). Lane owns j-pair {j0, j0+1}.
//   Stage 1: s[b] (20 KB) -> smem, fully coalesced; M -> smem.
//   Stage 2: lane builds s2[10] via 5 aligned LDS.128; 160 threads compute
//            t and store PRE-SPLATTED u64 {t,t} pairs (no per-use MOVs).
//   Stage 3: sweep 16 rows: LDS.64 broadcast of t-splat, 10 fma2 (split
//            accumulators), coalesced LDG.64 of G, v in acc[R] regs,
//            lane pair-sum -> psum_sm (no shuffles).
//   Stage 4: two-stage smem reduction -> inv; single-pass STG.64 epilogue.
// ---------------------------------------------------------------------------
__global__ __launch_bounds__(THREADS, 3) void attn_main(
    const float* __restrict__ s,
    const float* __restrict__ Gmat,
    float* __restrict__ out) {
    __shared__ float s_sm[NN * INF];        // 20 KB, s[b] row-major
    __shared__ float Msh[INF * INF];
    __shared__ u64   t2_sm[R][INF];         // pre-splatted {t,t}
    __shared__ float psum_sm[R][THREADS + 1];  // lane pair-sums (pad 257)
    __shared__ float part_sm[R][16];
    __shared__ float inv_sm[R];

    const int tid = threadIdx.x;
    const int b = blockIdx.x / CHUNKS;
    const int row0 = (blockIdx.x % CHUNKS) * R;

    // ---- Stage 1: coalesced staging of s[b] + M
    {
        const float* sb = s + (size_t)b * NN * INF;
#pragma unroll
        for (int k = 0; k < (NN * INF) / THREADS; k++)
            s_sm[tid + k * THREADS] = sb[tid + k * THREADS];
    }
    if (tid < INF * INF) Msh[tid] = g_M[tid];
    __syncthreads();

    // ---- Stage 2a: lane-private packed s for its j-pair (5 LDS.128)
    const int w = tid >> 5, l = tid & 31;
    const int j0 = (w << 6) + (l << 1);
    u64 s2[INF];
    {
        const float4* p4 = (const float4*)(s_sm + j0 * INF);  // 16B-aligned
        float4 f0 = p4[0], f1 = p4[1], f2 = p4[2], f3 = p4[3], f4v = p4[4];
        s2[0] = pk2(f0.x, f2.z);  s2[1] = pk2(f0.y, f2.w);
        s2[2] = pk2(f0.z, f3.x);  s2[3] = pk2(f0.w, f3.y);
        s2[4] = pk2(f1.x, f3.z);  s2[5] = pk2(f1.y, f3.w);
        s2[6] = pk2(f1.z, f4v.x); s2[7] = pk2(f1.w, f4v.y);
        s2[8] = pk2(f2.x, f4v.z); s2[9] = pk2(f2.y, f4v.w);
    }

    // ---- Stage 2b: t[r][o] = s[row0+r] . M[:,o], stored pre-splatted
    if (tid < R * INF) {
        const int r = tid / INF, o = tid % INF;
        const float* srow = s_sm + (row0 + r) * INF;
        float acc = 0.0f;
#pragma unroll
        for (int ll = 0; ll < INF; ll++)
            acc = fmaf(srow[ll], Msh[ll * INF + o], acc);
        t2_sm[r][o] = pk2(acc, acc);
    }
    __syncthreads();

    // ---- Stage 3: main sweep over 16 rows
    const float* gp = Gmat + ((size_t)b * NN + row0) * NN + j0;
    u64 acc[R];

#pragma unroll
    for (int r = 0; r < R; r++) {
        u64 da = pk2(0.0f, 0.0f);
        u64 db = pk2(0.0f, 0.0f);
#pragma unroll
        for (int i = 0; i < INF; i += 2) {
            da = fma2(s2[i],     t2_sm[r][i],     da);   // LDS.64 broadcast
            db = fma2(s2[i + 1], t2_sm[r][i + 1], db);
        }
        const u64 d = add2f(da, db);
        const u64 g = *(const u64*)(gp + (size_t)r * NN);   // LDG.64
        const u64 v = mul2f(mul2f(d, d), g);
        acc[r] = v;

        float lo, hi;
        upk2(v, lo, hi);
        psum_sm[r][tid] = lo + hi;            // no shuffles
    }
    __syncthreads();

    // ---- Stage 4a: 256 threads, each sums 16 strided lane-sums of one row
    {
        const int r = tid >> 4, seg = tid & 15;
        float a = 0.0f;
#pragma unroll
        for (int k = 0; k < 16; k++)
            a += psum_sm[r][seg + (k << 4)];
        part_sm[r][seg] = a;
    }
    __syncthreads();

    // ---- Stage 4b: 16 threads finish, compute 1/(sum+1e-3)
    if (tid < R) {
        float ssum = 0.0f;
#pragma unroll
        for (int k = 0; k < 16; k++) ssum += part_sm[tid][k];
        inv_sm[tid] = 1.0f / (ssum + 0.001f);
    }
    __syncthreads();

    // ---- normalized stores (STG.64)
    float* op = out + ((size_t)b * NN + row0) * NN + j0;
#pragma unroll
    for (int r = 0; r < R; r++) {
        const float iv = inv_sm[r];
        *(u64*)(op + (size_t)r * NN) = mul2f(acc[r], pk2(iv, iv));
    }
}

// ---------------------------------------------------------------------------
extern "C" void kernel_launch(void* const* d_in, const int* in_sizes, int n_in,
                              void* d_out, int out_size) {
    const float* s    = (const float*)d_in[0];
    const float* Gmat = (const float*)d_in[1];
    const float* Qw   = (const float*)d_in[2];
    const float* Kw   = (const float*)d_in[3];
    float* out = (float*)d_out;

    compute_M_kernel<<<1, 128>>>(Qw, Kw);
    attn_main<<<BB * CHUNKS, THREADS>>>(s, Gmat, out);
}

// round 11
// speedup vs baseline: 1.1121x; 1.1121x over previous
#include <cuda_runtime.h>

#define BB 256
#define NN 512
#define INF 10
#define HIDF 32
#define R 16                      // rows per block
#define WARPS 8
#define THREADS (WARPS * 32)
#define CHUNKS (NN / R)           // 32
#define SP 11                     // padded s row stride (coprime with 32)

typedef unsigned long long u64;

// ---- packed f32x2 helpers (sm_103a FFMA2 path, PTX-only) -------------------
__device__ __forceinline__ u64 pk2(float lo, float hi) {
    u64 r; asm("mov.b64 %0,{%1,%2};" : "=l"(r) : "f"(lo), "f"(hi)); return r;
}
__device__ __forceinline__ void upk2(u64 v, float& lo, float& hi) {
    asm("mov.b64 {%0,%1},%2;" : "=f"(lo), "=f"(hi) : "l"(v));
}
__device__ __forceinline__ u64 fma2(u64 a, u64 b, u64 c) {
    u64 r; asm("fma.rn.f32x2 %0,%1,%2,%3;" : "=l"(r) : "l"(a), "l"(b), "l"(c)); return r;
}
__device__ __forceinline__ u64 mul2f(u64 a, u64 b) {
    u64 r; asm("mul.rn.f32x2 %0,%1,%2;" : "=l"(r) : "l"(a), "l"(b)); return r;
}
__device__ __forceinline__ u64 add2f(u64 a, u64 b) {
    u64 r; asm("add.rn.f32x2 %0,%1,%2;" : "=l"(r) : "l"(a), "l"(b)); return r;
}

// ---------------------------------------------------------------------------
// Block = (batch b, 16-row chunk). 8 warps: half = w>>2 selects columns
// [256*half, 256*half+256); rg = w&3 selects rows [4rg, 4rg+4).
//   Stage 1: s[b] -> smem row-major with pad-11 stride, fully coalesced;
//            M = Q K^T computed in-block (threads 0..99).
//   Stage 2: t = s.M for the 16 rows (threads 0..159); warps pack t into
//            row-pair registers tpA/tpB (warp-uniform).
//   Stage 3: u<8 column sweep. Each scalar LDS of s[j][i] (conflict-free,
//            stride 11) feeds FOUR rows via 2 fma2. G loads pack row-pairs.
//            v stays in acc[16] u64 registers (single-pass normalization).
//   Stage 4: packed shuffle row-sums, half-combine in smem, normalized
//            coalesced STG.32 epilogue.
// ---------------------------------------------------------------------------
__global__ __launch_bounds__(THREADS, 2) void attn_main(
    const float* __restrict__ s,
    const float* __restrict__ Gmat,
    const float* __restrict__ Qw,
    const float* __restrict__ Kw,
    float* __restrict__ out) {
    __shared__ float s_sm[NN * SP];      // s[b], row-major, stride 11 (22.5 KB)
    __shared__ float Msh[INF * INF];
    __shared__ float t_sm[R][INF];
    __shared__ float psum[R][2];
    __shared__ float inv_sm[R];

    const int tid = threadIdx.x;
    const int b = blockIdx.x / CHUNKS;
    const int row0 = (blockIdx.x % CHUNKS) * R;

    // ---- Stage 1: coalesced staging of s[b] (pad-11) + M in-block
    {
        const float* sb = s + (size_t)b * NN * INF;
#pragma unroll
        for (int k = 0; k < (NN * INF) / THREADS; k++) {
            const int idx = tid + k * THREADS;
            s_sm[(idx / INF) * SP + (idx % INF)] = sb[idx];
        }
    }
    if (tid < INF * INF) {
        const int a = tid / INF, p = tid % INF;
        float acc = 0.0f;
#pragma unroll
        for (int m = 0; m < HIDF; m++)
            acc = fmaf(Qw[a * HIDF + m], Kw[p * HIDF + m], acc);
        Msh[tid] = acc;
    }
    __syncthreads();

    // ---- Stage 2: t[r][o] = s[row0+r] . M[:,o]  (160 threads)
    if (tid < R * INF) {
        const int r = tid / INF, o = tid % INF;
        const float* srow = s_sm + (row0 + r) * SP;
        float acc = 0.0f;
#pragma unroll
        for (int l = 0; l < INF; l++)
            acc = fmaf(srow[l], Msh[l * INF + o], acc);
        t_sm[r][o] = acc;
    }
    __syncthreads();

    // ---- warp decomposition
    const int w = tid >> 5, lane = tid & 31;
    const int half = w >> 2;            // column half
    const int rg = w & 3;               // row group (4 rows)
    const int r0 = rg * 4;              // first of the warp's 4 rows
    const int jbase = (half << 8) + lane;

    u64 tpA[INF], tpB[INF];             // row-pair packed t (warp-uniform)
#pragma unroll
    for (int i = 0; i < INF; i++) {
        tpA[i] = pk2(t_sm[r0 + 0][i], t_sm[r0 + 1][i]);
        tpB[i] = pk2(t_sm[r0 + 2][i], t_sm[r0 + 3][i]);
    }

    const float* g0 = Gmat + ((size_t)b * NN + row0 + r0) * NN + jbase;
    const float* g1 = g0 + NN;
    const float* g2 = g0 + 2 * NN;
    const float* g3 = g0 + 3 * NN;

    // ---- Stage 3: column sweep, one s-read feeds 4 rows
    u64 accA[8], accB[8];
    u64 sumA = pk2(0.0f, 0.0f);
    u64 sumB = pk2(0.0f, 0.0f);

#pragma unroll
    for (int u = 0; u < 8; u++) {
        const int j = jbase + (u << 5);
        const float* sj = s_sm + j * SP;

        u64 dA = pk2(0.0f, 0.0f);
        u64 dB = pk2(0.0f, 0.0f);
#pragma unroll
        for (int i = 0; i < INF; i++) {
            const float sv = sj[i];           // LDS.32, stride-11: conflict-free
            const u64 sp = pk2(sv, sv);
            dA = fma2(tpA[i], sp, dA);
            dB = fma2(tpB[i], sp, dB);
        }
        const int uo = u << 5;
        const u64 gA = pk2(g0[uo], g1[uo]);   // coalesced LDG.32 x4
        const u64 gB = pk2(g2[uo], g3[uo]);
        const u64 vA = mul2f(mul2f(dA, dA), gA);
        const u64 vB = mul2f(mul2f(dB, dB), gB);
        accA[u] = vA;
        accB[u] = vB;
        sumA = add2f(sumA, vA);
        sumB = add2f(sumB, vB);
    }

    // ---- Stage 4: packed shuffle reduction + half-combine
#pragma unroll
    for (int off = 16; off > 0; off >>= 1) {
        sumA = add2f(sumA, __shfl_xor_sync(0xffffffffu, sumA, off));
        sumB = add2f(sumB, __shfl_xor_sync(0xffffffffu, sumB, off));
    }
    if (lane == 0) {
        float a0, a1, b0, b1;
        upk2(sumA, a0, a1);
        upk2(sumB, b0, b1);
        psum[r0 + 0][half] = a0;
        psum[r0 + 1][half] = a1;
        psum[r0 + 2][half] = b0;
        psum[r0 + 3][half] = b1;
    }
    __syncthreads();
    if (tid < R)
        inv_sm[tid] = 1.0f / (psum[tid][0] + psum[tid][1] + 0.001f);
    __syncthreads();

    // ---- normalized coalesced stores
    const u64 ivA = pk2(inv_sm[r0 + 0], inv_sm[r0 + 1]);
    const u64 ivB = pk2(inv_sm[r0 + 2], inv_sm[r0 + 3]);
    float* o0 = out + ((size_t)b * NN + row0 + r0) * NN + jbase;
    float* o1 = o0 + NN;
    float* o2 = o0 + 2 * NN;
    float* o3 = o0 + 3 * NN;

#pragma unroll
    for (int u = 0; u < 8; u++) {
        const int uo = u << 5;
        float x, y;
        upk2(mul2f(accA[u], ivA), x, y);
        o0[uo] = x;
        o1[uo] = y;
        upk2(mul2f(accB[u], ivB), x, y);
        o2[uo] = x;
        o3[uo] = y;
    }
}

// ---------------------------------------------------------------------------
extern "C" void kernel_launch(void* const* d_in, const int* in_sizes, int n_in,
                              void* d_out, int out_size) {
    const float* s    = (const float*)d_in[0];
    const float* Gmat = (const float*)d_in[1];
    const float* Qw   = (const float*)d_in[2];
    const float* Kw   = (const float*)d_in[3];
    float* out = (float*)d_out;

    attn_main<<<BB * CHUNKS, THREADS>>>(s, Gmat, Qw, Kw, out);
}